// round 2
// baseline (speedup 1.0000x reference)
#include <cuda_runtime.h>
#include <math.h>

#define S_LEN  128
#define D_DIM  25
#define E_DIM  301
#define NCLS   5
#define KPAD   304      // E padded to multiple of 8
#define MSTR   50048    // vocab padded to multiple of 128
#define BSTR   704      // B-matrix col stride (covers 11 tiles of 64)
#define PSTR   672      // Ptable row stride (floats), 16B aligned
#define VOCAB_MAX 50000

typedef unsigned long long ull;

// Precomputed per-vocab table:
//   cols [0,625):   Ptable[w, i*25+j] = sum_e emb[w,e]*A[i,e,j] + V[j,i]
//   cols [625,650): ctable[w, d]      = sum_e emb[w,e]*W[e,d]   + b[d]
__device__ float g_Ptable[(size_t)VOCAB_MAX * PSTR];
__device__ float g_embT[(size_t)KPAD * MSTR];     // transposed, padded embeddings
__device__ float g_Bpack[(size_t)KPAD * BSTR];    // packed B matrix [k][n]

// ---------------------------------------------------------------------------
// Prep 1: transpose emb [vocab x 301] -> g_embT [304 x 50048] (zero padded)
// ---------------------------------------------------------------------------
__global__ void transpose_emb(const float* __restrict__ emb, int vocab)
{
    __shared__ float tile[32][33];
    const int m0 = blockIdx.x * 32;
    const int k0 = blockIdx.y * 32;
    #pragma unroll
    for (int j = threadIdx.y; j < 32; j += 8) {
        int m = m0 + j, k = k0 + threadIdx.x;
        tile[j][threadIdx.x] = (m < vocab && k < E_DIM) ? emb[(size_t)m * E_DIM + k] : 0.f;
    }
    __syncthreads();
    #pragma unroll
    for (int j = threadIdx.y; j < 32; j += 8) {
        int k = k0 + j, m = m0 + threadIdx.x;
        if (k < KPAD) g_embT[(size_t)k * MSTR + m] = tile[threadIdx.x][j];
    }
}

// ---------------------------------------------------------------------------
// Prep 2: pack B matrix: Bpack[k][n<625] = A[n/25][k][n%25]; [625..650)=W[k][n-625]
// ---------------------------------------------------------------------------
__global__ void build_bpack(const float* __restrict__ A, const float* __restrict__ W)
{
    int idx = blockIdx.x * blockDim.x + threadIdx.x;
    if (idx >= KPAD * BSTR) return;
    int k = idx / BSTR, n = idx % BSTR;
    float v = 0.f;
    if (k < E_DIM) {
        if (n < 625)      v = A[(size_t)(n / 25) * (E_DIM * 25) + k * 25 + (n % 25)];
        else if (n < 650) v = W[(size_t)k * 25 + (n - 625)];
    }
    g_Bpack[idx] = v;
}

// ---------------------------------------------------------------------------
// GEMM via fma.rn.f32x2: [50048 x 304] x [304 x 704-tiled] -> g_Ptable
// BM=128, BN=64, BK=8, 128 threads, 8x8 per thread (m packed in pairs).
// B stored DUPLICATED in smem so FFMA2 needs no pack instructions.
// ---------------------------------------------------------------------------
#define FMA2(d, a, b) asm("fma.rn.f32x2 %0, %1, %2, %0;" : "+l"(d) : "l"(a), "l"(b))

__global__ void __launch_bounds__(128, 4)
gemm_f32x2(const float* __restrict__ V, const float* __restrict__ bvec, int vocab)
{
    __shared__ __align__(16) float As[2][8][128];
    __shared__ __align__(16) float Bs2[2][8][128];   // duplicated: [2n]=[2n+1]=b[n]
    __shared__ float addv[64];

    const int tid = threadIdx.x;
    const int m0 = blockIdx.y * 128;
    const int n0 = blockIdx.x * 64;
    const int row = tid >> 3;      // 0..15  -> m block of 8
    const int col = tid & 7;       // 0..7   -> n block of 8

    // fold-in additive terms (V transposed for bilinear cols, bias for linear)
    if (tid < 64) {
        int n = n0 + tid;
        float a = 0.f;
        if (n < 625)      a = V[(n % 25) * 25 + (n / 25)];
        else if (n < 650) a = bvec[n - 625];
        addv[tid] = a;
    }

    // global load mappings
    const int ak0 = tid >> 5;            // A: id = tid + i*128 -> k=id>>5, m4=id&31
    const int am0 = (tid & 31) * 4;
    const int bk  = tid >> 4;            // B: k = tid>>4, n4 = tid&15
    const int bn  = (tid & 15) * 4;

    float4 pa0, pa1, pb;
    {   // prefetch kt = 0
        pa0 = *(const float4*)(g_embT + (size_t)(ak0)     * MSTR + m0 + am0);
        pa1 = *(const float4*)(g_embT + (size_t)(ak0 + 4) * MSTR + m0 + am0);
        pb  = *(const float4*)(g_Bpack + (size_t)bk * BSTR + n0 + bn);
    }
    // store tile 0
    *(float4*)&As[0][ak0][am0]     = pa0;
    *(float4*)&As[0][ak0 + 4][am0] = pa1;
    *(float4*)&Bs2[0][bk][bn * 2]     = make_float4(pb.x, pb.x, pb.y, pb.y);
    *(float4*)&Bs2[0][bk][bn * 2 + 4] = make_float4(pb.z, pb.z, pb.w, pb.w);
    __syncthreads();

    ull acc[4][8];
    #pragma unroll
    for (int u = 0; u < 4; ++u)
        #pragma unroll
        for (int v = 0; v < 8; ++v) acc[u][v] = 0ull;

    const int KT = KPAD / 8;   // 38
    int cur = 0;
    for (int kt = 0; kt < KT; ++kt) {
        if (kt + 1 < KT) {
            const size_t kb = (size_t)(kt + 1) * 8;
            pa0 = *(const float4*)(g_embT + (kb + ak0)     * MSTR + m0 + am0);
            pa1 = *(const float4*)(g_embT + (kb + ak0 + 4) * MSTR + m0 + am0);
            pb  = *(const float4*)(g_Bpack + (kb + bk) * BSTR + n0 + bn);
        }
        #pragma unroll
        for (int kk = 0; kk < 8; ++kk) {
            ulonglong2 a01 = *(const ulonglong2*)&As[cur][kk][row * 8];
            ulonglong2 a23 = *(const ulonglong2*)&As[cur][kk][row * 8 + 4];
            ull a_[4] = {a01.x, a01.y, a23.x, a23.y};
            #pragma unroll
            for (int v2 = 0; v2 < 4; ++v2) {
                ulonglong2 b2 = *(const ulonglong2*)&Bs2[cur][kk][col * 16 + v2 * 4];
                #pragma unroll
                for (int u = 0; u < 4; ++u) {
                    FMA2(acc[u][v2 * 2],     a_[u], b2.x);
                    FMA2(acc[u][v2 * 2 + 1], a_[u], b2.y);
                }
            }
        }
        if (kt + 1 < KT) {
            cur ^= 1;
            *(float4*)&As[cur][ak0][am0]     = pa0;
            *(float4*)&As[cur][ak0 + 4][am0] = pa1;
            *(float4*)&Bs2[cur][bk][bn * 2]     = make_float4(pb.x, pb.x, pb.y, pb.y);
            *(float4*)&Bs2[cur][bk][bn * 2 + 4] = make_float4(pb.z, pb.z, pb.w, pb.w);
            __syncthreads();
        }
    }

    // epilogue: unpack m-pairs, add V/bias fold, store float4 along n
    #pragma unroll
    for (int u = 0; u < 8; ++u) {
        int m = m0 + row * 8 + u;
        if (m >= vocab) continue;
        float* orow = g_Ptable + (size_t)m * PSTR;
        const int u2 = u >> 1, half = u & 1;
        #pragma unroll
        for (int v0 = 0; v0 < 8; v0 += 4) {
            int n = n0 + col * 8 + v0;
            if (n >= 656) continue;
            float4 o;
            float2 f0 = ((float2*)&acc[u2][v0])[0];
            float2 f1 = ((float2*)&acc[u2][v0 + 1])[0];
            float2 f2 = ((float2*)&acc[u2][v0 + 2])[0];
            float2 f3 = ((float2*)&acc[u2][v0 + 3])[0];
            o.x = (half ? f0.y : f0.x) + addv[col * 8 + v0];
            o.y = (half ? f1.y : f1.x) + addv[col * 8 + v0 + 1];
            o.z = (half ? f2.y : f2.x) + addv[col * 8 + v0 + 2];
            o.w = (half ? f3.y : f3.x) + addv[col * 8 + v0 + 3];
            *(float4*)&orow[n] = o;
        }
    }
}

// ---------------------------------------------------------------------------
// Recurrence: one warp per batch element, double-buffered P-row gather.
//   h_new[i] = tanh( c[i] + sum_j P[i,j]*h[j] )   (V, b already folded)
// ---------------------------------------------------------------------------
#define WPB 8
__global__ void __launch_bounds__(256)
recurrence_kernel(const int* __restrict__ words,
                  const float* __restrict__ outW,
                  const float* __restrict__ outb,
                  float* __restrict__ out,
                  int B)
{
    __shared__ __align__(16) float Pbuf[WPB][2][656];
    __shared__ float hs[WPB][32];

    const int lane = threadIdx.x & 31;
    const int w    = threadIdx.x >> 5;
    const int b    = blockIdx.x * WPB + w;
    if (b >= B) return;   // uniform per warp

    const int* wrow = words + (size_t)b * S_LEN;
    float* hb = hs[w];
    hb[lane] = (lane == D_DIM - 1) ? 1.f : 0.f;

    // per-lane chunks: q = lane + 32*i, i<6, valid while q<164 (656 floats)
    float4 r[6];
    {
        int word = wrow[0];
        const float4* src = (const float4*)(g_Ptable + (size_t)word * PSTR);
        #pragma unroll
        for (int i = 0; i < 6; ++i) { int q = lane + 32 * i; if (q < 164) r[i] = src[q]; }
        float4* dst = (float4*)Pbuf[w][0];
        #pragma unroll
        for (int i = 0; i < 6; ++i) { int q = lane + 32 * i; if (q < 164) dst[q] = r[i]; }
    }
    __syncwarp();

    int cur = 0;
    for (int t = 0; t < S_LEN; ++t) {
        const bool more = (t + 1 < S_LEN);
        if (more) {   // issue gather for t+1 (independent of h) before compute
            int word = wrow[t + 1];
            const float4* src = (const float4*)(g_Ptable + (size_t)word * PSTR);
            #pragma unroll
            for (int i = 0; i < 6; ++i) { int q = lane + 32 * i; if (q < 164) r[i] = src[q]; }
        }
        float hn = 0.f;
        if (lane < D_DIM) {
            const float* pc = Pbuf[w][cur];
            float acc = pc[625 + lane];
            const float* prow = pc + lane * D_DIM;
            #pragma unroll
            for (int j = 0; j < D_DIM; ++j)
                acc = fmaf(prow[j], hb[j], acc);
            hn = tanhf(acc);
        }
        __syncwarp();
        if (lane < D_DIM) hb[lane] = hn;
        if (more) {
            float4* dst = (float4*)Pbuf[w][cur ^ 1];
            #pragma unroll
            for (int i = 0; i < 6; ++i) { int q = lane + 32 * i; if (q < 164) dst[q] = r[i]; }
            cur ^= 1;
        }
        __syncwarp();
    }

    if (lane < NCLS) {
        float acc = outb[lane];
        #pragma unroll
        for (int i = 0; i < D_DIM; ++i)
            acc = fmaf(outW[lane * D_DIM + i], hb[i], acc);
        out[(size_t)b * NCLS + lane] = 1.f / (1.f + expf(-acc));
    }
}

// ---------------------------------------------------------------------------
extern "C" void kernel_launch(void* const* d_in, const int* in_sizes, int n_in,
                              void* d_out, int out_size)
{
    // inputs: words, [batch_size], emb_table, A, W, V, b, out_W, out_b
    const int o = (n_in >= 9) ? 1 : 0;
    const int*   words = (const int*)  d_in[0];
    const float* emb   = (const float*)d_in[1 + o];
    const float* A     = (const float*)d_in[2 + o];
    const float* W     = (const float*)d_in[3 + o];
    const float* V     = (const float*)d_in[4 + o];
    const float* bvec  = (const float*)d_in[5 + o];
    const float* outW  = (const float*)d_in[6 + o];
    const float* outb  = (const float*)d_in[7 + o];
    float* out = (float*)d_out;

    const int B = in_sizes[0] / S_LEN;
    int vocab   = in_sizes[1 + o] / E_DIM;
    if (vocab > VOCAB_MAX) vocab = VOCAB_MAX;

    // 1) prep: transpose emb, pack B
    transpose_emb<<<dim3(MSTR / 32, KPAD / 32 + 1), dim3(32, 8)>>>(emb, vocab);
    build_bpack<<<(KPAD * BSTR + 255) / 256, 256>>>(A, W);

    // 2) GEMM -> per-vocab table
    gemm_f32x2<<<dim3(11, (vocab + 127) / 128), 128>>>(V, bvec, vocab);

    // 3) recurrence + head
    recurrence_kernel<<<(B + WPB - 1) / WPB, WPB * 32>>>(words, outW, outb, out, B);
}

// round 5
// speedup vs baseline: 3.1947x; 3.1947x over previous
#include <cuda_runtime.h>
#include <cuda_fp16.h>
#include <cstdint>
#include <math.h>

#define S_LEN  128
#define D_DIM  25
#define NCLS   5
#define E_DIM  301
#define KSEG   320                 // padded K per segment (301 -> 320)
#define MROWS  50048               // vocab padded to 128
#define NPAD   768                 // 656 padded to 128*6
#define KBIG   960                 // 3 segments
#define PSTR   672                 // Ptable row stride (floats)
#define VOCAB_MAX 50000
#define BM     128
#define BN     128
#define BK     64
#define NCHUNK 15                  // 960/64
#define PLANE  ((size_t)MROWS * KSEG)
#define RSCALE 2048.0f             // residual-plane scale (2^11)

// Segment order (correction first, main last):
//   chunks 0-4:   a0   x b1'   (B offset 0)    -> acc (at 2048x)
//   chunks 5-9:   a1'  x b0    (B offset 320)  -> acc (at 2048x)
//   [acc *= 1/2048]
//   chunks 10-14: a0   x b0    (B offset 640)  -> acc
// Final acc = a0*b0 + (a0*b1 + a1*b0)  with full fp16-normal-range residuals.

// ---------------- device globals (no runtime alloc allowed) ----------------
__device__ __align__(16) float  g_Ptable[(size_t)VOCAB_MAX * PSTR];
__device__ __align__(16) __half g_Ah[2 * PLANE];                // planes: a0, a1*2048
__device__ __align__(16) __half g_Bh[(size_t)NPAD * KBIG];      // rows: [b1*2048 | b0 | b0]

// ---------------- helpers ----------------
__device__ __forceinline__ uint32_t smem_u32(const void* p) {
    uint32_t a;
    asm("{ .reg .u64 t; cvta.to.shared.u64 t, %1; cvt.u32.u64 %0, t; }" : "=r"(a) : "l"(p));
    return a;
}
// 16B-granular xor swizzle for 128B rows
#define SWZ(row, cg) ((((uint32_t)(row)) << 7) + ((((cg) ^ ((row) & 7))) << 4))

#define CP16(dst, src) asm volatile("cp.async.cg.shared.global [%0], [%1], 16;" :: "r"(dst), "l"(src))
#define CP_COMMIT()    asm volatile("cp.async.commit_group;" ::: "memory")
#define CP_WAIT2()     asm volatile("cp.async.wait_group 2;" ::: "memory")

#define LDSM4(r, a) asm volatile( \
    "ldmatrix.sync.aligned.m8n8.x4.shared.b16 {%0,%1,%2,%3}, [%4];" \
    : "=r"((r)[0]), "=r"((r)[1]), "=r"((r)[2]), "=r"((r)[3]) : "r"(a))

#define MMA16816(c, a, b0, b1) asm volatile( \
    "mma.sync.aligned.m16n8k16.row.col.f32.f16.f16.f32 " \
    "{%0,%1,%2,%3}, {%4,%5,%6,%7}, {%8,%9}, {%0,%1,%2,%3};" \
    : "+f"((c)[0]), "+f"((c)[1]), "+f"((c)[2]), "+f"((c)[3]) \
    : "r"((a)[0]), "r"((a)[1]), "r"((a)[2]), "r"((a)[3]), "r"(b0), "r"(b1))

// ---------------------------------------------------------------------------
// Prep 1: split emb into fp16 planes a0 and a1*2048, [m][320], zero padded
// ---------------------------------------------------------------------------
__global__ void split_A(const float* __restrict__ emb, int vocab)
{
    size_t idx = (size_t)blockIdx.x * blockDim.x + threadIdx.x;
    if (idx >= PLANE) return;
    int k = (int)(idx % KSEG);
    size_t m = idx / KSEG;
    float x = (m < (size_t)vocab && k < E_DIM) ? emb[m * E_DIM + k] : 0.f;
    __half a0 = __float2half_rn(x);
    float r = (x - __half2float(a0)) * RSCALE;
    g_Ah[idx]         = a0;
    g_Ah[idx + PLANE] = __float2half_rn(r);
}

// ---------------------------------------------------------------------------
// Prep 2: B rows [n][960]: [0,320): b1*2048, [320,640): b0, [640,960): b0
//   Bmat[k][n<625] = A[n/25][k][n%25]; Bmat[k][625+d] = W[k][d]
// ---------------------------------------------------------------------------
__global__ void split_B(const float* __restrict__ A, const float* __restrict__ W)
{
    int idx = blockIdx.x * blockDim.x + threadIdx.x;
    if (idx >= NPAD * KSEG) return;
    int n = idx / KSEG, k = idx % KSEG;
    float v = 0.f;
    if (k < E_DIM) {
        if (n < 625)      v = A[((size_t)(n / 25) * E_DIM + k) * 25 + (n % 25)];
        else if (n < 650) v = W[(size_t)k * 25 + (n - 625)];
    }
    __half b0 = __float2half_rn(v);
    float r = (v - __half2float(b0)) * RSCALE;
    __half* row = g_Bh + (size_t)n * KBIG;
    row[k]       = __float2half_rn(r);
    row[320 + k] = b0;
    row[640 + k] = b0;
}

// ---------------------------------------------------------------------------
// HMMA GEMM: [50048 x 960] x [960 x 768] -> g_Ptable (with V/bias fold).
// CTA 128x128, 8 warps (4m x 2n), warp tile 32x64, BK=64, 3-stage cp.async.
// Correction segments first; acc rescaled by 1/2048 before main segment.
// ---------------------------------------------------------------------------
#define SM_STAGE 32768
#define SM_ADDV  (3 * SM_STAGE)
#define SM_TOTAL (3 * SM_STAGE + 512)

__global__ void __launch_bounds__(256)
gemm_hmma(const float* __restrict__ V, const float* __restrict__ bvec, int vocab)
{
    extern __shared__ __align__(128) char smem[];
    const uint32_t sbase = smem_u32(smem);
    float* addv = (float*)(smem + SM_ADDV);

    const int tid  = threadIdx.x;
    const int w    = tid >> 5, lane = tid & 31;
    const int m0   = blockIdx.y * BM;
    const int n0   = blockIdx.x * BN;

    if (tid < BN) {
        int n = n0 + tid;
        float a = 0.f;
        if (n < 625)      a = V[(n % 25) * 25 + (n / 25)];
        else if (n < 650) a = bvec[n - 625];
        addv[tid] = a;
    }

    // ---- cp.async mapping: thread t loads 4x16B in A row t/2 and B row t/2 ----
    const int lrow = tid >> 1;
    const int lcg0 = (tid & 1) * 4;

    auto load_chunk = [&](int c, int st) {
        // A plane: chunks 5-9 use a1' (plane 1); others a0 (plane 0)
        const size_t apl = (c >= 5 && c < 10) ? PLANE : 0;
        const int koff = (c % 5) * BK;
        const __half* asrc = g_Ah + apl + (size_t)(m0 + lrow) * KSEG + koff + lcg0 * 8;
        const uint32_t abase = sbase + st * SM_STAGE;
        #pragma unroll
        for (int i = 0; i < 4; ++i)
            CP16(abase + SWZ(lrow, lcg0 + i), asrc + i * 8);
        // B segment offset: chunks 0-4 -> 0 (b1'), 5-9 -> 320 (b0), 10-14 -> 640 (b0)
        const int bseg = (c < 5) ? 0 : ((c < 10) ? 320 : 640);
        const __half* bsrc = g_Bh + (size_t)(n0 + lrow) * KBIG + bseg + koff + lcg0 * 8;
        const uint32_t bbase = sbase + st * SM_STAGE + 16384;
        #pragma unroll
        for (int i = 0; i < 4; ++i)
            CP16(bbase + SWZ(lrow, lcg0 + i), bsrc + i * 8);
    };

    float acc[2][8][4];
    #pragma unroll
    for (int mi = 0; mi < 2; ++mi)
        #pragma unroll
        for (int nj = 0; nj < 8; ++nj)
            #pragma unroll
            for (int q = 0; q < 4; ++q) acc[mi][nj][q] = 0.f;

    const int rowa = (w & 3) * 32 + (lane & 15);
    const int rowb = (w >> 2) * 64 + (lane & 15);
    const int cgl  = lane >> 4;

    load_chunk(0, 0); CP_COMMIT();
    load_chunk(1, 1); CP_COMMIT();
    load_chunk(2, 2); CP_COMMIT();

    for (int c = 0; c < NCHUNK; ++c) {
        const int st = c % 3;
        CP_WAIT2();
        __syncthreads();
        if (c == 10) {
            // corrections (2048x scale) done -> rescale before main segment
            const float inv = 1.0f / RSCALE;
            #pragma unroll
            for (int mi = 0; mi < 2; ++mi)
                #pragma unroll
                for (int nj = 0; nj < 8; ++nj)
                    #pragma unroll
                    for (int q = 0; q < 4; ++q) acc[mi][nj][q] *= inv;
        }
        const uint32_t abase = sbase + st * SM_STAGE;
        const uint32_t bbase = abase + 16384;
        #pragma unroll
        for (int kt = 0; kt < 4; ++kt) {
            uint32_t af[2][4], bf[4][4];
            const int cg = 2 * kt + cgl;
            #pragma unroll
            for (int mi = 0; mi < 2; ++mi)
                LDSM4(af[mi], abase + SWZ(rowa + mi * 16, cg));
            #pragma unroll
            for (int nj = 0; nj < 4; ++nj)
                LDSM4(bf[nj], bbase + SWZ(rowb + nj * 16, cg));
            #pragma unroll
            for (int mi = 0; mi < 2; ++mi)
                #pragma unroll
                for (int n8 = 0; n8 < 8; ++n8)
                    MMA16816(acc[mi][n8], af[mi],
                             bf[n8 >> 1][n8 & 1], bf[n8 >> 1][2 + (n8 & 1)]);
        }
        __syncthreads();
        if (c + 3 < NCHUNK) load_chunk(c + 3, st);
        CP_COMMIT();
    }

    // ---- epilogue: add fold values, store float2 pairs ----
    #pragma unroll
    for (int mi = 0; mi < 2; ++mi) {
        const int r0 = m0 + (w & 3) * 32 + mi * 16 + (lane >> 2);
        #pragma unroll
        for (int n8 = 0; n8 < 8; ++n8) {
            const int ln = (w >> 2) * 64 + n8 * 8 + (lane & 3) * 2;
            const int n  = n0 + ln;
            if (n >= 656) continue;
            const float a0 = addv[ln], a1 = addv[ln + 1];
            if (r0 < vocab) {
                float2 v; v.x = acc[mi][n8][0] + a0; v.y = acc[mi][n8][1] + a1;
                *(float2*)(g_Ptable + (size_t)r0 * PSTR + n) = v;
            }
            if (r0 + 8 < vocab) {
                float2 v; v.x = acc[mi][n8][2] + a0; v.y = acc[mi][n8][3] + a1;
                *(float2*)(g_Ptable + (size_t)(r0 + 8) * PSTR + n) = v;
            }
        }
    }
}

// ---------------------------------------------------------------------------
// Recurrence (measured 112us): warp per batch element, double-buffered gather.
//   h_new = tanh(c + P h); fused sigmoid head. (V, b folded into table.)
// ---------------------------------------------------------------------------
#define WPB 8
__global__ void __launch_bounds__(256)
recurrence_kernel(const int* __restrict__ words,
                  const float* __restrict__ outW,
                  const float* __restrict__ outb,
                  float* __restrict__ out,
                  int B)
{
    __shared__ __align__(16) float Pbuf[WPB][2][656];
    __shared__ float hs[WPB][32];

    const int lane = threadIdx.x & 31;
    const int w    = threadIdx.x >> 5;
    const int b    = blockIdx.x * WPB + w;
    if (b >= B) return;

    const int* wrow = words + (size_t)b * S_LEN;
    float* hb = hs[w];
    hb[lane] = (lane == D_DIM - 1) ? 1.f : 0.f;

    float4 r[6];
    {
        int word = wrow[0];
        const float4* src = (const float4*)(g_Ptable + (size_t)word * PSTR);
        #pragma unroll
        for (int i = 0; i < 6; ++i) { int q = lane + 32 * i; if (q < 164) r[i] = src[q]; }
        float4* dst = (float4*)Pbuf[w][0];
        #pragma unroll
        for (int i = 0; i < 6; ++i) { int q = lane + 32 * i; if (q < 164) dst[q] = r[i]; }
    }
    __syncwarp();

    int cur = 0;
    for (int t = 0; t < S_LEN; ++t) {
        const bool more = (t + 1 < S_LEN);
        if (more) {
            int word = wrow[t + 1];
            const float4* src = (const float4*)(g_Ptable + (size_t)word * PSTR);
            #pragma unroll
            for (int i = 0; i < 6; ++i) { int q = lane + 32 * i; if (q < 164) r[i] = src[q]; }
        }
        float hn = 0.f;
        if (lane < D_DIM) {
            const float* pc = Pbuf[w][cur];
            float acc = pc[625 + lane];
            const float* prow = pc + lane * D_DIM;
            #pragma unroll
            for (int j = 0; j < D_DIM; ++j)
                acc = fmaf(prow[j], hb[j], acc);
            hn = tanhf(acc);
        }
        __syncwarp();
        if (lane < D_DIM) hb[lane] = hn;
        if (more) {
            float4* dst = (float4*)Pbuf[w][cur ^ 1];
            #pragma unroll
            for (int i = 0; i < 6; ++i) { int q = lane + 32 * i; if (q < 164) dst[q] = r[i]; }
            cur ^= 1;
        }
        __syncwarp();
    }

    if (lane < NCLS) {
        float acc = outb[lane];
        #pragma unroll
        for (int i = 0; i < D_DIM; ++i)
            acc = fmaf(outW[lane * D_DIM + i], hb[i], acc);
        out[(size_t)b * NCLS + lane] = 1.f / (1.f + expf(-acc));
    }
}

// ---------------------------------------------------------------------------
extern "C" void kernel_launch(void* const* d_in, const int* in_sizes, int n_in,
                              void* d_out, int out_size)
{
    // inputs: words, [batch_size], emb_table, A, W, V, b, out_W, out_b
    const int o = (n_in >= 9) ? 1 : 0;
    const int*   words = (const int*)  d_in[0];
    const float* emb   = (const float*)d_in[1 + o];
    const float* A     = (const float*)d_in[2 + o];
    const float* W     = (const float*)d_in[3 + o];
    const float* V     = (const float*)d_in[4 + o];
    const float* bvec  = (const float*)d_in[5 + o];
    const float* outW  = (const float*)d_in[6 + o];
    const float* outb  = (const float*)d_in[7 + o];
    float* out = (float*)d_out;

    const int B = in_sizes[0] / S_LEN;
    int vocab   = in_sizes[1 + o] / E_DIM;
    if (vocab > VOCAB_MAX) vocab = VOCAB_MAX;

    // prep: fp16 split planes (residuals scaled by 2048)
    split_A<<<(int)((PLANE + 255) / 256), 256>>>(emb, vocab);
    split_B<<<(NPAD * KSEG + 255) / 256, 256>>>(A, W);

    // tensor-core (HMMA) GEMM -> per-vocab table
    static bool cfg = false;
    if (!cfg) {
        cudaFuncSetAttribute(gemm_hmma, cudaFuncAttributeMaxDynamicSharedMemorySize, SM_TOTAL);
        cfg = true;
    }
    gemm_hmma<<<dim3(NPAD / BN, MROWS / BM), 256, SM_TOTAL>>>(V, bvec, vocab);

    // recurrence + head
    recurrence_kernel<<<(B + WPB - 1) / WPB, WPB * 32>>>(words, outW, outb, out, B);
}

// round 6
// speedup vs baseline: 3.6155x; 1.1317x over previous
#include <cuda_runtime.h>
#include <cuda_fp16.h>
#include <cstdint>
#include <math.h>

#define S_LEN  128
#define D_DIM  25
#define NCLS   5
#define E_DIM  301
#define KSEG   320                 // padded K per segment (301 -> 320)
#define MROWS  50048               // vocab padded to 128
#define NPAD   768                 // 656 padded to 128*6
#define KBIG   960                 // 3 segments
#define PSTR   672                 // Ptable row stride (floats)
#define VOCAB_MAX 50000
#define BM     128
#define BN     128
#define BK     64
#define NCHUNK 15                  // 960/64
#define PLANE  ((size_t)MROWS * KSEG)
#define RSCALE 2048.0f             // residual-plane scale (2^11)

// Segment order (correction first, main last):
//   chunks 0-4:   a0   x b1'   (B offset 0)    -> acc (at 2048x)
//   chunks 5-9:   a1'  x b0    (B offset 320)  -> acc (at 2048x)
//   [acc *= 1/2048]
//   chunks 10-14: a0   x b0    (B offset 640)  -> acc

// ---------------- device globals (no runtime alloc allowed) ----------------
__device__ __align__(16) float  g_Ptable[(size_t)VOCAB_MAX * PSTR];
__device__ __align__(16) __half g_Ah[2 * PLANE];                // planes: a0, a1*2048
__device__ __align__(16) __half g_Bh[(size_t)NPAD * KBIG];      // rows: [b1*2048 | b0 | b0]

// ---------------- helpers ----------------
__device__ __forceinline__ uint32_t smem_u32(const void* p) {
    uint32_t a;
    asm("{ .reg .u64 t; cvta.to.shared.u64 t, %1; cvt.u32.u64 %0, t; }" : "=r"(a) : "l"(p));
    return a;
}
// 16B-granular xor swizzle for 128B rows
#define SWZ(row, cg) ((((uint32_t)(row)) << 7) + ((((cg) ^ ((row) & 7))) << 4))

#define CP16(dst, src) asm volatile("cp.async.cg.shared.global [%0], [%1], 16;" :: "r"(dst), "l"(src))
#define CP_COMMIT()    asm volatile("cp.async.commit_group;" ::: "memory")
#define CP_WAIT1()     asm volatile("cp.async.wait_group 1;" ::: "memory")

#define LDSM4(r, a) asm volatile( \
    "ldmatrix.sync.aligned.m8n8.x4.shared.b16 {%0,%1,%2,%3}, [%4];" \
    : "=r"((r)[0]), "=r"((r)[1]), "=r"((r)[2]), "=r"((r)[3]) : "r"(a))

#define MMA16816(c, a, b0, b1) asm volatile( \
    "mma.sync.aligned.m16n8k16.row.col.f32.f16.f16.f32 " \
    "{%0,%1,%2,%3}, {%4,%5,%6,%7}, {%8,%9}, {%0,%1,%2,%3};" \
    : "+f"((c)[0]), "+f"((c)[1]), "+f"((c)[2]), "+f"((c)[3]) \
    : "r"((a)[0]), "r"((a)[1]), "r"((a)[2]), "r"((a)[3]), "r"(b0), "r"(b1))

// ---------------------------------------------------------------------------
// Prep 1: split emb into fp16 planes a0 and a1*2048, [m][320], zero padded
// ---------------------------------------------------------------------------
__global__ void split_A(const float* __restrict__ emb, int vocab)
{
    size_t idx = (size_t)blockIdx.x * blockDim.x + threadIdx.x;
    if (idx >= PLANE) return;
    int k = (int)(idx % KSEG);
    size_t m = idx / KSEG;
    float x = (m < (size_t)vocab && k < E_DIM) ? emb[m * E_DIM + k] : 0.f;
    __half a0 = __float2half_rn(x);
    float r = (x - __half2float(a0)) * RSCALE;
    g_Ah[idx]         = a0;
    g_Ah[idx + PLANE] = __float2half_rn(r);
}

// ---------------------------------------------------------------------------
// Prep 2: B rows [n][960]: [0,320): b1*2048, [320,640): b0, [640,960): b0
// ---------------------------------------------------------------------------
__global__ void split_B(const float* __restrict__ A, const float* __restrict__ W)
{
    int idx = blockIdx.x * blockDim.x + threadIdx.x;
    if (idx >= NPAD * KSEG) return;
    int n = idx / KSEG, k = idx % KSEG;
    float v = 0.f;
    if (k < E_DIM) {
        if (n < 625)      v = A[((size_t)(n / 25) * E_DIM + k) * 25 + (n % 25)];
        else if (n < 650) v = W[(size_t)k * 25 + (n - 625)];
    }
    __half b0 = __float2half_rn(v);
    float r = (v - __half2float(b0)) * RSCALE;
    __half* row = g_Bh + (size_t)n * KBIG;
    row[k]       = __float2half_rn(r);
    row[320 + k] = b0;
    row[640 + k] = b0;
}

// ---------------------------------------------------------------------------
// HMMA GEMM: 2-stage cp.async pipeline, 2 CTAs/SM for bubble hiding.
// CTA 128x128, 8 warps (4m x 2n), warp tile 32x64, BK=64.
// ---------------------------------------------------------------------------
#define SM_STAGE 32768
#define SM_ADDV  (2 * SM_STAGE)
#define SM_TOTAL (2 * SM_STAGE + 512)

__global__ void __launch_bounds__(256, 2)
gemm_hmma(const float* __restrict__ V, const float* __restrict__ bvec, int vocab)
{
    extern __shared__ __align__(128) char smem[];
    const uint32_t sbase = smem_u32(smem);
    float* addv = (float*)(smem + SM_ADDV);

    const int tid  = threadIdx.x;
    const int w    = tid >> 5, lane = tid & 31;
    const int m0   = blockIdx.y * BM;
    const int n0   = blockIdx.x * BN;

    if (tid < BN) {
        int n = n0 + tid;
        float a = 0.f;
        if (n < 625)      a = V[(n % 25) * 25 + (n / 25)];
        else if (n < 650) a = bvec[n - 625];
        addv[tid] = a;
    }

    // ---- cp.async mapping: thread t loads 4x16B in A row t/2 and B row t/2 ----
    const int lrow = tid >> 1;
    const int lcg0 = (tid & 1) * 4;

    auto load_chunk = [&](int c, int st) {
        const size_t apl = (c >= 5 && c < 10) ? PLANE : 0;
        const int koff = (c % 5) * BK;
        const __half* asrc = g_Ah + apl + (size_t)(m0 + lrow) * KSEG + koff + lcg0 * 8;
        const uint32_t abase = sbase + st * SM_STAGE;
        #pragma unroll
        for (int i = 0; i < 4; ++i)
            CP16(abase + SWZ(lrow, lcg0 + i), asrc + i * 8);
        const int bseg = (c < 5) ? 0 : ((c < 10) ? 320 : 640);
        const __half* bsrc = g_Bh + (size_t)(n0 + lrow) * KBIG + bseg + koff + lcg0 * 8;
        const uint32_t bbase = sbase + st * SM_STAGE + 16384;
        #pragma unroll
        for (int i = 0; i < 4; ++i)
            CP16(bbase + SWZ(lrow, lcg0 + i), bsrc + i * 8);
    };

    float acc[2][8][4];
    #pragma unroll
    for (int mi = 0; mi < 2; ++mi)
        #pragma unroll
        for (int nj = 0; nj < 8; ++nj)
            #pragma unroll
            for (int q = 0; q < 4; ++q) acc[mi][nj][q] = 0.f;

    const int rowa = (w & 3) * 32 + (lane & 15);
    const int rowb = (w >> 2) * 64 + (lane & 15);
    const int cgl  = lane >> 4;

    load_chunk(0, 0); CP_COMMIT();
    load_chunk(1, 1); CP_COMMIT();

    for (int c = 0; c < NCHUNK; ++c) {
        const int st = c & 1;
        CP_WAIT1();
        __syncthreads();
        if (c == 10) {
            const float inv = 1.0f / RSCALE;
            #pragma unroll
            for (int mi = 0; mi < 2; ++mi)
                #pragma unroll
                for (int nj = 0; nj < 8; ++nj)
                    #pragma unroll
                    for (int q = 0; q < 4; ++q) acc[mi][nj][q] *= inv;
        }
        const uint32_t abase = sbase + st * SM_STAGE;
        const uint32_t bbase = abase + 16384;
        #pragma unroll
        for (int kt = 0; kt < 4; ++kt) {
            uint32_t af[2][4], bf[4][4];
            const int cg = 2 * kt + cgl;
            #pragma unroll
            for (int mi = 0; mi < 2; ++mi)
                LDSM4(af[mi], abase + SWZ(rowa + mi * 16, cg));
            #pragma unroll
            for (int nj = 0; nj < 4; ++nj)
                LDSM4(bf[nj], bbase + SWZ(rowb + nj * 16, cg));
            #pragma unroll
            for (int mi = 0; mi < 2; ++mi)
                #pragma unroll
                for (int n8 = 0; n8 < 8; ++n8)
                    MMA16816(acc[mi][n8], af[mi],
                             bf[n8 >> 1][n8 & 1], bf[n8 >> 1][2 + (n8 & 1)]);
        }
        __syncthreads();
        if (c + 2 < NCHUNK) load_chunk(c + 2, st);
        CP_COMMIT();
    }

    // ---- epilogue: add fold values, store float2 pairs ----
    #pragma unroll
    for (int mi = 0; mi < 2; ++mi) {
        const int r0 = m0 + (w & 3) * 32 + mi * 16 + (lane >> 2);
        #pragma unroll
        for (int n8 = 0; n8 < 8; ++n8) {
            const int ln = (w >> 2) * 64 + n8 * 8 + (lane & 3) * 2;
            const int n  = n0 + ln;
            if (n >= 656) continue;
            const float a0 = addv[ln], a1 = addv[ln + 1];
            if (r0 < vocab) {
                float2 v; v.x = acc[mi][n8][0] + a0; v.y = acc[mi][n8][1] + a1;
                *(float2*)(g_Ptable + (size_t)r0 * PSTR + n) = v;
            }
            if (r0 + 8 < vocab) {
                float2 v; v.x = acc[mi][n8][2] + a0; v.y = acc[mi][n8][3] + a1;
                *(float2*)(g_Ptable + (size_t)(r0 + 8) * PSTR + n) = v;
            }
        }
    }
}

// ---------------------------------------------------------------------------
// Recurrence: warp per batch element, cp.async 3-buffer pipeline (2-step
// lookahead). h_new = tanh(c + P h); fused sigmoid head.
// ---------------------------------------------------------------------------
#define WPB 4
__global__ void __launch_bounds__(128)
recurrence_kernel(const int* __restrict__ words,
                  const float* __restrict__ outW,
                  const float* __restrict__ outb,
                  float* __restrict__ out,
                  int B)
{
    __shared__ __align__(16) float Pbuf[WPB][3][656];
    __shared__ float hs[WPB][32];

    const int lane = threadIdx.x & 31;
    const int w    = threadIdx.x >> 5;
    const int b    = blockIdx.x * WPB + w;
    if (b >= B) return;   // uniform per warp

    const int* wrow = words + (size_t)b * S_LEN;
    float* hb = hs[w];
    hb[lane] = (lane == D_DIM - 1) ? 1.f : 0.f;

    // issue cp.async gather of P row for step t into buffer s
    auto issue = [&](int t, int s) {
        const char* src = (const char*)(g_Ptable + (size_t)wrow[t] * PSTR);
        const uint32_t dst = smem_u32(&Pbuf[w][s][0]);
        #pragma unroll
        for (int i = 0; i < 6; ++i) {
            int q = lane + 32 * i;
            if (q < 164) CP16(dst + q * 16, src + q * 16);
        }
    };

    issue(0, 0); CP_COMMIT();
    issue(1, 1); CP_COMMIT();

    for (int t = 0; t < S_LEN; ++t) {
        CP_WAIT1();          // group t complete (t+1 may still be in flight)
        __syncwarp();
        const float* pc = Pbuf[w][t % 3];
        float hn = 0.f;
        if (lane < D_DIM) {
            float acc = pc[625 + lane];
            const float* prow = pc + lane * D_DIM;
            #pragma unroll
            for (int j = 0; j < D_DIM; ++j)
                acc = fmaf(prow[j], hb[j], acc);
            hn = tanhf(acc);
        }
        __syncwarp();
        if (lane < D_DIM) hb[lane] = hn;
        __syncwarp();
        if (t + 2 < S_LEN) issue(t + 2, (t + 2) % 3);
        CP_COMMIT();
    }

    if (lane < NCLS) {
        float acc = outb[lane];
        #pragma unroll
        for (int i = 0; i < D_DIM; ++i)
            acc = fmaf(outW[lane * D_DIM + i], hb[i], acc);
        out[(size_t)b * NCLS + lane] = 1.f / (1.f + expf(-acc));
    }
}

// ---------------------------------------------------------------------------
extern "C" void kernel_launch(void* const* d_in, const int* in_sizes, int n_in,
                              void* d_out, int out_size)
{
    // inputs: words, [batch_size], emb_table, A, W, V, b, out_W, out_b
    const int o = (n_in >= 9) ? 1 : 0;
    const int*   words = (const int*)  d_in[0];
    const float* emb   = (const float*)d_in[1 + o];
    const float* A     = (const float*)d_in[2 + o];
    const float* W     = (const float*)d_in[3 + o];
    const float* V     = (const float*)d_in[4 + o];
    const float* bvec  = (const float*)d_in[5 + o];
    const float* outW  = (const float*)d_in[6 + o];
    const float* outb  = (const float*)d_in[7 + o];
    float* out = (float*)d_out;

    const int B = in_sizes[0] / S_LEN;
    int vocab   = in_sizes[1 + o] / E_DIM;
    if (vocab > VOCAB_MAX) vocab = VOCAB_MAX;

    // prep: fp16 split planes (residuals scaled by 2048)
    split_A<<<(int)((PLANE + 255) / 256), 256>>>(emb, vocab);
    split_B<<<(NPAD * KSEG + 255) / 256, 256>>>(A, W);

    // tensor-core (HMMA) GEMM -> per-vocab table
    static bool cfg = false;
    if (!cfg) {
        cudaFuncSetAttribute(gemm_hmma, cudaFuncAttributeMaxDynamicSharedMemorySize, SM_TOTAL);
        cfg = true;
    }
    gemm_hmma<<<dim3(NPAD / BN, MROWS / BM), 256, SM_TOTAL>>>(V, bvec, vocab);

    // recurrence + head
    recurrence_kernel<<<(B + WPB - 1) / WPB, WPB * 32>>>(words, outW, outb, out, B);
}